// round 10
// baseline (speedup 1.0000x reference)
#include <cuda_runtime.h>

// GeGate: out = y if (0 < y <= 1) else 0, y = x * w[col] + b[col]
// x: (8192, 4096) fp32 = 8388608 float4s.
// 2048 blocks x 256 threads; TSTRIDE = 524288 float4s = multiple of D4, so a
// thread's 16 strided float4s all share one column -> w/b loaded ONCE per
// thread (quarters broadcast-LDG L1 traffic vs 4-wide version). Body is a
// forced (non-unrolled) loop of 4 quads: 4 front-batched streaming loads +
// 4 streaming stores per iteration, keeping regs ~40 and occupancy high.

#define D_DIM 4096
#define D4    (D_DIM / 4)            // 1024 float4 columns
#define D4_MASK (D4 - 1)
#define THREADS 256
#define BLOCKS  2048
#define TSTRIDE (THREADS * BLOCKS)   // 524288, multiple of D4
#define QUADS   4                    // 4 quads * 4 float4 = 16 float4/thread

__device__ __forceinline__ float4 gate4(float4 xv, float4 wv, float4 bv) {
    float4 y;
    y.x = fmaf(xv.x, wv.x, bv.x);
    y.y = fmaf(xv.y, wv.y, bv.y);
    y.z = fmaf(xv.z, wv.z, bv.z);
    y.w = fmaf(xv.w, wv.w, bv.w);
    y.x = (y.x > 0.0f && y.x <= 1.0f) ? y.x : 0.0f;
    y.y = (y.y > 0.0f && y.y <= 1.0f) ? y.y : 0.0f;
    y.z = (y.z > 0.0f && y.z <= 1.0f) ? y.z : 0.0f;
    y.w = (y.w > 0.0f && y.w <= 1.0f) ? y.w : 0.0f;
    return y;
}

__global__ void __launch_bounds__(THREADS) gegate_kernel(
    const float4* __restrict__ x,
    const float4* __restrict__ w,
    const float4* __restrict__ b,
    float4* __restrict__ out)
{
    int i = blockIdx.x * THREADS + threadIdx.x;   // 0 .. TSTRIDE-1
    int c4 = i & D4_MASK;                         // column, invariant for all 16

    float4 wv = __ldg(&w[c4]);
    float4 bv = __ldg(&b[c4]);

    const float4* xp = x + i;
    float4* op = out + i;

    #pragma unroll 1
    for (int q = 0; q < QUADS; ++q) {
        // 4 independent streaming loads front-batched (MLP_p1 = 4)
        float4 x0 = __ldcs(xp + 0 * TSTRIDE);
        float4 x1 = __ldcs(xp + 1 * TSTRIDE);
        float4 x2 = __ldcs(xp + 2 * TSTRIDE);
        float4 x3 = __ldcs(xp + 3 * TSTRIDE);

        __stcs(op + 0 * TSTRIDE, gate4(x0, wv, bv));
        __stcs(op + 1 * TSTRIDE, gate4(x1, wv, bv));
        __stcs(op + 2 * TSTRIDE, gate4(x2, wv, bv));
        __stcs(op + 3 * TSTRIDE, gate4(x3, wv, bv));

        xp += 4 * TSTRIDE;
        op += 4 * TSTRIDE;
    }
}

extern "C" void kernel_launch(void* const* d_in, const int* in_sizes, int n_in,
                              void* d_out, int out_size)
{
    const float4* x = (const float4*)d_in[0];
    const float4* w = (const float4*)d_in[1];
    const float4* b = (const float4*)d_in[2];
    float4* out = (float4*)d_out;

    // out_size = 8192*4096 = 33554432 elems = 8388608 float4 = 16 * TSTRIDE
    gegate_kernel<<<BLOCKS, THREADS>>>(x, w, b, out);
}